// round 14
// baseline (speedup 1.0000x reference)
#include <cuda_runtime.h>
#include <math.h>
#include <stdint.h>

#define T_TOK 16384
#define DMODEL 1280
#define NHEAD 16
#define HDIM 80
#define IDIM 5120
#define NSEG 16
#define LSEG 1024

// ---------------- scratch (static device globals; no allocation) -------------
__device__ float g_X  [(size_t)T_TOK * DMODEL];
__device__ float g_QKV[(size_t)T_TOK * 3 * DMODEL];
__device__ float g_ATT[(size_t)T_TOK * DMODEL];
__device__ float g_H  [(size_t)T_TOK * DMODEL];
__device__ float g_Y  [(size_t)T_TOK * DMODEL];
__device__ float g_G  [(size_t)T_TOK * IDIM];
__device__ float g_Wq [(size_t)3 * DMODEL * DMODEL];
__device__ float g_Wp [(size_t)DMODEL * DMODEL];
__device__ float g_W1 [(size_t)IDIM * DMODEL];
__device__ float g_W2 [(size_t)DMODEL * IDIM];

__device__ __forceinline__ uint32_t f2tf32(float x) {
    uint32_t r;
    asm("cvt.rna.tf32.f32 %0, %1;" : "=r"(r) : "f"(x));
    return r;
}
__device__ __forceinline__ float tf32r(float x) { return __uint_as_float(f2tf32(x)); }

// fast exp on the FMA pipe (softmax args are <= 0)
__device__ __forceinline__ float fexp(float x) {
    float y = fmaxf(x * 1.4426950408889634f, -126.f);
    float r = floorf(y);
    float f = y - r;
    const float c1 = 0.69314718056f, c2 = 0.24022650696f, c3 = 0.05550410866f,
                c4 = 0.00961812911f, c5 = 0.00133335581f, c6 = 0.00015403530f;
    float p = 1.f + f * (c1 + f * (c2 + f * (c3 + f * (c4 + f * (c5 + f * c6)))));
    return p * __int_as_float(((int)r + 127) << 23);
}

// ---------------- weight pre-round -------------------------------------------
__global__ __launch_bounds__(256) void round_tf32_kernel(
    const float* __restrict__ src, float* __restrict__ dst, int n4)
{
    int i = blockIdx.x * blockDim.x + threadIdx.x;
    if (i >= n4) return;
    float4 v = ((const float4*)src)[i];
    v.x = tf32r(v.x); v.y = tf32r(v.y); v.z = tf32r(v.z); v.w = tf32r(v.w);
    ((float4*)dst)[i] = v;
}

// ---------------- LayerNorm (emits tf32-rounded) ------------------------------
__global__ __launch_bounds__(256) void ln_kernel(
    const float* __restrict__ x, const float* __restrict__ w,
    const float* __restrict__ b, float* __restrict__ y)
{
    int row = blockIdx.x;
    const float* xr = x + (size_t)row * DMODEL;
    float v[5];
    float s = 0.f, s2 = 0.f;
#pragma unroll
    for (int j = 0; j < 5; ++j) {
        v[j] = xr[threadIdx.x + j * 256];
        s += v[j];
        s2 += v[j] * v[j];
    }
#pragma unroll
    for (int o = 16; o; o >>= 1) {
        s  += __shfl_xor_sync(0xffffffffu, s,  o);
        s2 += __shfl_xor_sync(0xffffffffu, s2, o);
    }
    __shared__ float sh[16];
    int wid = threadIdx.x >> 5, lane = threadIdx.x & 31;
    if (!lane) { sh[wid] = s; sh[wid + 8] = s2; }
    __syncthreads();
    if (threadIdx.x == 0) {
        float S = 0.f, S2 = 0.f;
#pragma unroll
        for (int i = 0; i < 8; ++i) { S += sh[i]; S2 += sh[i + 8]; }
        sh[0] = S; sh[8] = S2;
    }
    __syncthreads();
    float mean = sh[0] * (1.f / DMODEL);
    float var  = sh[8] * (1.f / DMODEL) - mean * mean;
    float inv  = rsqrtf(var + 1e-6f);
    float* yr = y + (size_t)row * DMODEL;
#pragma unroll
    for (int j = 0; j < 5; ++j) {
        int c = threadIdx.x + j * 256;
        yr[c] = tf32r((v[j] - mean) * inv * w[c] + b[c]);
    }
}

// ---------------- RoPE (in place on q,k halves of QKV) ------------------------
__global__ __launch_bounds__(256) void rope_kernel(
    float* __restrict__ QKV, const float* __restrict__ cosp,
    const float* __restrict__ sinp)
{
    int idx = blockIdx.x * blockDim.x + threadIdx.x;
    if (idx >= T_TOK * NHEAD * 40) return;
    int d = idx % 40;
    int h = (idx / 40) % NHEAD;
    int t = idx / (40 * NHEAD);
    float c1 = cosp[t * HDIM + d],      s1 = sinp[t * HDIM + d];
    float c2 = cosp[t * HDIM + d + 40], s2 = sinp[t * HDIM + d + 40];
    size_t base = (size_t)t * (3 * DMODEL) + h * HDIM;
    float q1 = QKV[base + d], q2 = QKV[base + d + 40];
    QKV[base + d]      = q1 * c1 - q2 * s1;
    QKV[base + d + 40] = q2 * c2 + q1 * s2;
    base += DMODEL;
    float k1 = QKV[base + d], k2 = QKV[base + d + 40];
    QKV[base + d]      = k1 * c1 - k2 * s1;
    QKV[base + d + 40] = k2 * c2 + k1 * s2;
}

// ---------------- tf32 mma helper ---------------------------------------------
__device__ __forceinline__ void mma_tf32(float* c, const uint32_t* a, const uint32_t* b) {
    asm volatile(
        "mma.sync.aligned.m16n8k8.row.col.f32.tf32.tf32.f32 "
        "{%0,%1,%2,%3}, {%4,%5,%6,%7}, {%8,%9}, {%0,%1,%2,%3};"
        : "+f"(c[0]), "+f"(c[1]), "+f"(c[2]), "+f"(c[3])
        : "r"(a[0]), "r"(a[1]), "r"(a[2]), "r"(a[3]), "r"(b[0]), "r"(b[1]));
}

// ---------------- Tensorized flash attention (Round-8 proven) -----------------
#define KP 84
#define VP 88
#define PP 68
#define ATTN_SMEM ((64 * KP + 64 * VP + 4 * 16 * PP) * 4)

__global__ __launch_bounds__(128) void attn_mma_kernel(
    const float* __restrict__ QKV, float* __restrict__ O)
{
    extern __shared__ float sm[];
    float* Ks = sm;
    float* Vs = sm + 64 * KP;
    int tid = threadIdx.x;
    int wid = tid >> 5, lane = tid & 31;
    int g = lane >> 2, t = lane & 3;
    float* Ps = sm + 64 * KP + 64 * VP + wid * 16 * PP;

    int qt = blockIdx.x, head = blockIdx.y, seg = blockIdx.z;
    int q0 = seg * LSEG + qt * 64;
    const float scale = 0.11180339887498948f;

    for (int i = tid; i < 64 * 20; i += 128) {
        int row = i / 20, c4 = (i % 20) * 4;
        float4 v = *(const float4*)(QKV + (size_t)(q0 + row) * (3 * DMODEL) + head * HDIM + c4);
        float* p = Ks + row * KP + c4;
        p[0] = v.x * scale; p[1] = v.y * scale; p[2] = v.z * scale; p[3] = v.w * scale;
    }
    __syncthreads();

    uint32_t qa[10][4];
    {
        int r0 = wid * 16 + g;
#pragma unroll
        for (int ks = 0; ks < 10; ++ks) {
            qa[ks][0] = __float_as_uint(Ks[r0 * KP + ks * 8 + t]);
            qa[ks][1] = __float_as_uint(Ks[(r0 + 8) * KP + ks * 8 + t]);
            qa[ks][2] = __float_as_uint(Ks[r0 * KP + ks * 8 + t + 4]);
            qa[ks][3] = __float_as_uint(Ks[(r0 + 8) * KP + ks * 8 + t + 4]);
        }
    }
    __syncthreads();

    float oacc[10][4];
#pragma unroll
    for (int nt = 0; nt < 10; ++nt)
#pragma unroll
        for (int q = 0; q < 4; ++q) oacc[nt][q] = 0.f;
    float m0 = -1e30f, m1 = -1e30f, l0 = 0.f, l1 = 0.f;

    for (int kt = 0; kt < LSEG / 64; ++kt) {
        int k0 = seg * LSEG + kt * 64;
        for (int i = tid; i < 64 * 20; i += 128) {
            int row = i / 20, c4 = (i % 20) * 4;
            const float* base = QKV + (size_t)(k0 + row) * (3 * DMODEL) + head * HDIM + c4;
            float4 kv = *(const float4*)(base + DMODEL);
            float* kp = Ks + row * KP + c4;
            kp[0] = kv.x; kp[1] = kv.y; kp[2] = kv.z; kp[3] = kv.w;
            float4 vv = *(const float4*)(base + 2 * DMODEL);
            *(float4*)(Vs + row * VP + c4) = vv;
        }
        __syncthreads();

        float sacc[8][4];
#pragma unroll
        for (int nt = 0; nt < 8; ++nt)
#pragma unroll
            for (int q = 0; q < 4; ++q) sacc[nt][q] = 0.f;
#pragma unroll
        for (int ks = 0; ks < 10; ++ks) {
#pragma unroll
            for (int nt = 0; nt < 8; ++nt) {
                uint32_t bf[2];
                bf[0] = __float_as_uint(Ks[(nt * 8 + g) * KP + ks * 8 + t]);
                bf[1] = __float_as_uint(Ks[(nt * 8 + g) * KP + ks * 8 + t + 4]);
                mma_tf32(sacc[nt], qa[ks], bf);
            }
        }

        float mx0 = sacc[0][0], mx1 = sacc[0][2];
#pragma unroll
        for (int nt = 0; nt < 8; ++nt) {
            mx0 = fmaxf(mx0, fmaxf(sacc[nt][0], sacc[nt][1]));
            mx1 = fmaxf(mx1, fmaxf(sacc[nt][2], sacc[nt][3]));
        }
        mx0 = fmaxf(mx0, __shfl_xor_sync(0xffffffffu, mx0, 1));
        mx0 = fmaxf(mx0, __shfl_xor_sync(0xffffffffu, mx0, 2));
        mx1 = fmaxf(mx1, __shfl_xor_sync(0xffffffffu, mx1, 1));
        mx1 = fmaxf(mx1, __shfl_xor_sync(0xffffffffu, mx1, 2));
        float nm0 = fmaxf(m0, mx0), nm1 = fmaxf(m1, mx1);
        float corr0 = fexp(m0 - nm0), corr1 = fexp(m1 - nm1);
        float ps0 = 0.f, ps1 = 0.f;
#pragma unroll
        for (int nt = 0; nt < 8; ++nt) {
            float p0 = fexp(sacc[nt][0] - nm0);
            float p1 = fexp(sacc[nt][1] - nm0);
            float p2 = fexp(sacc[nt][2] - nm1);
            float p3 = fexp(sacc[nt][3] - nm1);
            ps0 += p0 + p1;
            ps1 += p2 + p3;
            *(float2*)(Ps + g * PP + nt * 8 + 2 * t) = make_float2(p0, p1);
            *(float2*)(Ps + (g + 8) * PP + nt * 8 + 2 * t) = make_float2(p2, p3);
        }
        ps0 += __shfl_xor_sync(0xffffffffu, ps0, 1);
        ps0 += __shfl_xor_sync(0xffffffffu, ps0, 2);
        ps1 += __shfl_xor_sync(0xffffffffu, ps1, 1);
        ps1 += __shfl_xor_sync(0xffffffffu, ps1, 2);
        l0 = l0 * corr0 + ps0;
        l1 = l1 * corr1 + ps1;
        m0 = nm0; m1 = nm1;
#pragma unroll
        for (int nt = 0; nt < 10; ++nt) {
            oacc[nt][0] *= corr0; oacc[nt][1] *= corr0;
            oacc[nt][2] *= corr1; oacc[nt][3] *= corr1;
        }
        __syncwarp();

#pragma unroll
        for (int ks = 0; ks < 8; ++ks) {
            uint32_t af[4];
            af[0] = __float_as_uint(Ps[g * PP + ks * 8 + t]);
            af[1] = __float_as_uint(Ps[(g + 8) * PP + ks * 8 + t]);
            af[2] = __float_as_uint(Ps[g * PP + ks * 8 + t + 4]);
            af[3] = __float_as_uint(Ps[(g + 8) * PP + ks * 8 + t + 4]);
#pragma unroll
            for (int nt = 0; nt < 10; ++nt) {
                uint32_t bf[2];
                bf[0] = __float_as_uint(Vs[(ks * 8 + t) * VP + nt * 8 + g]);
                bf[1] = __float_as_uint(Vs[(ks * 8 + t + 4) * VP + nt * 8 + g]);
                mma_tf32(oacc[nt], af, bf);
            }
        }
        __syncthreads();
    }

    float inv0 = 1.f / l0, inv1 = 1.f / l1;
    int orow = q0 + wid * 16 + g;
#pragma unroll
    for (int nt = 0; nt < 10; ++nt) {
        int col = head * HDIM + nt * 8 + 2 * t;
        *(float2*)(O + (size_t)orow * DMODEL + col) =
            make_float2(tf32r(oacc[nt][0] * inv0), tf32r(oacc[nt][1] * inv0));
        *(float2*)(O + (size_t)(orow + 8) * DMODEL + col) =
            make_float2(tf32r(oacc[nt][2] * inv1), tf32r(oacc[nt][3] * inv1));
    }
}

// --- TF32 GEMM v4: CTA 128x128, 4 warps, warp 64x64, 3-stage, SINGLE sync -----
// Ring safety: compute(c) reads stage c%3; issue targets (c+2)%3; the
// top-of-loop __syncthreads fences compute(c-1), so no stage is overwritten
// while any warp still reads it. 110.6KB smem/CTA -> 2 CTAs/SM.
__device__ __forceinline__ void cp_async16(uint32_t saddr, const void* gptr) {
    asm volatile("cp.async.cg.shared.global [%0], [%1], 16;" :: "r"(saddr), "l"(gptr));
}

#define PITCH 36
#define STAGE_WORDS (2 * 128 * PITCH)   // A + B tile per stage (9216 words)
#define GEMM_SMEM (3 * STAGE_WORDS * 4) // 110592 bytes

__global__ __launch_bounds__(128) void gemm_tf32_pipe(
    const float* __restrict__ A, const float* __restrict__ B,
    const float* __restrict__ bias, const float* __restrict__ res,
    float* __restrict__ C, int M, int N, int K, int epi)
{
    extern __shared__ uint32_t smem[];
    uint32_t smem_base = (uint32_t)__cvta_generic_to_shared(smem);

    int tid = threadIdx.x;
    int wid = tid >> 5, lane = tid & 31;
    int g = lane >> 2, t = lane & 3;
    int mrow0 = (wid >> 1) * 64;     // 2 warps along M
    int ncol0 = (wid & 1) * 64;      // 2 warps along N

    const float* Ag = A + (size_t)(blockIdx.y * 128) * K;
    const float* Bg = B + (size_t)(blockIdx.x * 128) * K;

    int ldrow = tid >> 3;            // 0..15
    int ldkq  = (tid & 7) << 2;      // 0,4,..28

    float acc[4][8][4];
#pragma unroll
    for (int mt = 0; mt < 4; ++mt)
#pragma unroll
        for (int nt = 0; nt < 8; ++nt)
#pragma unroll
            for (int q = 0; q < 4; ++q) acc[mt][nt][q] = 0.f;

    const int NC = K >> 5;

    auto issue = [&](int c, int s) {
        int k0 = c << 5;
        uint32_t sa = smem_base + (uint32_t)s * (STAGE_WORDS * 4);
        uint32_t sb = sa + 128 * PITCH * 4;
#pragma unroll
        for (int i = 0; i < 8; ++i) {
            int row = ldrow + i * 16;
            uint32_t off = ((uint32_t)row * PITCH + ldkq) * 4;
            cp_async16(sa + off, Ag + (size_t)row * K + k0 + ldkq);
            cp_async16(sb + off, Bg + (size_t)row * K + k0 + ldkq);
        }
        asm volatile("cp.async.commit_group;");
    };

    issue(0, 0);
    issue(1, 1);

    for (int c = 0; c < NC; ++c) {
        asm volatile("cp.async.wait_group 1;");  // chunk c arrived (this thread)
        __syncthreads();                          // all threads' chunk-c data visible;
                                                  // also fences compute(c-1)
        if (c + 2 < NC) issue(c + 2, (c + 2) % 3);
        else asm volatile("cp.async.commit_group;");

        const uint32_t* Asp = smem + (size_t)(c % 3) * STAGE_WORDS;
        const uint32_t* Bsp = Asp + 128 * PITCH;
#pragma unroll
        for (int ks = 0; ks < 4; ++ks) {
            int kb = ks * 8 + t;
            uint32_t af[4][4], bf[8][2];
#pragma unroll
            for (int mt = 0; mt < 4; ++mt) {
                int r = mrow0 + mt * 16 + g;
                af[mt][0] = Asp[r * PITCH + kb];
                af[mt][1] = Asp[(r + 8) * PITCH + kb];
                af[mt][2] = Asp[r * PITCH + kb + 4];
                af[mt][3] = Asp[(r + 8) * PITCH + kb + 4];
            }
#pragma unroll
            for (int nt = 0; nt < 8; ++nt) {
                int cc = ncol0 + nt * 8 + g;
                bf[nt][0] = Bsp[cc * PITCH + kb];
                bf[nt][1] = Bsp[cc * PITCH + kb + 4];
            }
#pragma unroll
            for (int mt = 0; mt < 4; ++mt)
#pragma unroll
                for (int nt = 0; nt < 8; ++nt)
                    mma_tf32(acc[mt][nt], af[mt], bf[nt]);
        }
    }

    // epilogue: c0:(g,2t) c1:(g,2t+1) c2:(g+8,2t) c3:(g+8,2t+1)
#pragma unroll
    for (int mt = 0; mt < 4; ++mt) {
#pragma unroll
        for (int nt = 0; nt < 8; ++nt) {
            int row = blockIdx.y * 128 + mrow0 + mt * 16 + g;
            int col = blockIdx.x * 128 + ncol0 + nt * 8 + 2 * t;
            float b0 = bias[col], b1 = bias[col + 1];
#pragma unroll
            for (int half = 0; half < 2; ++half) {
                int r = row + half * 8;
                float v0 = acc[mt][nt][half * 2 + 0] + b0;
                float v1 = acc[mt][nt][half * 2 + 1] + b1;
                if (epi == 1) {
                    const float* rp = res + (size_t)r * N + col;
                    v0 += rp[0];
                    v1 += rp[1];
                } else if (epi == 2) {
                    v0 = tf32r(v0 * (1.f / (1.f + __expf(-v0))));
                    v1 = tf32r(v1 * (1.f / (1.f + __expf(-v1))));
                }
                *(float2*)(C + (size_t)r * N + col) = make_float2(v0, v1);
            }
        }
    }
}

// ---------------- launch ------------------------------------------------------
extern "C" void kernel_launch(void* const* d_in, const int* in_sizes, int n_in,
                              void* d_out, int out_size)
{
    const float* hidden = (const float*)d_in[0];
    const float* cosp   = (const float*)d_in[1];
    const float* sinp   = (const float*)d_in[2];
    const float* ln1w   = (const float*)d_in[3];
    const float* ln1b   = (const float*)d_in[4];
    const float* ln2w   = (const float*)d_in[5];
    const float* ln2b   = (const float*)d_in[6];
    const float* qkvw   = (const float*)d_in[7];
    const float* qkvb   = (const float*)d_in[8];
    const float* projw  = (const float*)d_in[9];
    const float* projb  = (const float*)d_in[10];
    const float* fc1w   = (const float*)d_in[11];
    const float* fc1b   = (const float*)d_in[12];
    const float* fc2w   = (const float*)d_in[13];
    const float* fc2b   = (const float*)d_in[14];
    float* out = (float*)d_out;

    void *pX, *pQKV, *pATT, *pH, *pY, *pG, *pWq, *pWp, *pW1, *pW2;
    cudaGetSymbolAddress(&pX, g_X);
    cudaGetSymbolAddress(&pQKV, g_QKV);
    cudaGetSymbolAddress(&pATT, g_ATT);
    cudaGetSymbolAddress(&pH, g_H);
    cudaGetSymbolAddress(&pY, g_Y);
    cudaGetSymbolAddress(&pG, g_G);
    cudaGetSymbolAddress(&pWq, g_Wq);
    cudaGetSymbolAddress(&pWp, g_Wp);
    cudaGetSymbolAddress(&pW1, g_W1);
    cudaGetSymbolAddress(&pW2, g_W2);
    float* X = (float*)pX;
    float* QKV = (float*)pQKV;
    float* ATT = (float*)pATT;
    float* Hb = (float*)pH;
    float* Y = (float*)pY;
    float* G = (float*)pG;
    float* Wq = (float*)pWq;
    float* Wp = (float*)pWp;
    float* W1 = (float*)pW1;
    float* W2 = (float*)pW2;

    static bool attr_set = false;
    if (!attr_set) {
        cudaFuncSetAttribute(gemm_tf32_pipe,
                             cudaFuncAttributeMaxDynamicSharedMemorySize, GEMM_SMEM);
        cudaFuncSetAttribute(attn_mma_kernel,
                             cudaFuncAttributeMaxDynamicSharedMemorySize, ATTN_SMEM);
        attr_set = true;
    }

    // 0. pre-round weights to tf32
    {
        int n4;
        n4 = 3 * DMODEL * DMODEL / 4;
        round_tf32_kernel<<<(n4 + 255) / 256, 256>>>(qkvw, Wq, n4);
        n4 = DMODEL * DMODEL / 4;
        round_tf32_kernel<<<(n4 + 255) / 256, 256>>>(projw, Wp, n4);
        n4 = IDIM * DMODEL / 4;
        round_tf32_kernel<<<(n4 + 255) / 256, 256>>>(fc1w, W1, n4);
        round_tf32_kernel<<<(n4 + 255) / 256, 256>>>(fc2w, W2, n4);
    }

    // 1. ln1
    ln_kernel<<<T_TOK, 256>>>(hidden, ln1w, ln1b, X);
    // 2. qkv = X @ qkv_w^T + qkv_b
    gemm_tf32_pipe<<<dim3(3 * DMODEL / 128, T_TOK / 128), 128, GEMM_SMEM>>>(
        X, Wq, qkvb, nullptr, QKV, T_TOK, 3 * DMODEL, DMODEL, 0);
    // 3. rope
    rope_kernel<<<(T_TOK * NHEAD * 40 + 255) / 256, 256>>>(QKV, cosp, sinp);
    // 4. tensorized attention
    attn_mma_kernel<<<dim3(LSEG / 64, NHEAD, NSEG), 128, ATTN_SMEM>>>(QKV, ATT);
    // 5. h = hidden + ATT @ proj_w^T + proj_b
    gemm_tf32_pipe<<<dim3(DMODEL / 128, T_TOK / 128), 128, GEMM_SMEM>>>(
        ATT, Wp, projb, hidden, Hb, T_TOK, DMODEL, DMODEL, 1);
    // 6. ln2
    ln_kernel<<<T_TOK, 256>>>(Hb, ln2w, ln2b, Y);
    // 7. G = silu(Y @ fc1_w^T + fc1_b)
    gemm_tf32_pipe<<<dim3(IDIM / 128, T_TOK / 128), 128, GEMM_SMEM>>>(
        Y, W1, fc1b, nullptr, G, T_TOK, IDIM, DMODEL, 2);
    // 8. out = h + G @ fc2_w^T + fc2_b
    gemm_tf32_pipe<<<dim3(DMODEL / 128, T_TOK / 128), 128, GEMM_SMEM>>>(
        G, W2, fc2b, Hb, out, T_TOK, DMODEL, IDIM, 1);
}

// round 17
// speedup vs baseline: 1.0513x; 1.0513x over previous
#include <cuda_runtime.h>
#include <math.h>
#include <stdint.h>

#define T_TOK 16384
#define DMODEL 1280
#define NHEAD 16
#define HDIM 80
#define IDIM 5120
#define NSEG 16
#define LSEG 1024

// ---------------- scratch (static device globals; no allocation) -------------
__device__ float g_X  [(size_t)T_TOK * DMODEL];
__device__ float g_QKV[(size_t)T_TOK * 3 * DMODEL];
__device__ float g_ATT[(size_t)T_TOK * DMODEL];
__device__ float g_H  [(size_t)T_TOK * DMODEL];
__device__ float g_Y  [(size_t)T_TOK * DMODEL];
__device__ float g_G  [(size_t)T_TOK * IDIM];
__device__ float g_Wq [(size_t)3 * DMODEL * DMODEL];
__device__ float g_Wp [(size_t)DMODEL * DMODEL];
__device__ float g_W1 [(size_t)IDIM * DMODEL];
__device__ float g_W2 [(size_t)DMODEL * IDIM];

__device__ __forceinline__ uint32_t f2tf32(float x) {
    uint32_t r;
    asm("cvt.rna.tf32.f32 %0, %1;" : "=r"(r) : "f"(x));
    return r;
}
__device__ __forceinline__ float tf32r(float x) { return __uint_as_float(f2tf32(x)); }

// fast exp on the FMA pipe (softmax args are <= 0)
__device__ __forceinline__ float fexp(float x) {
    float y = fmaxf(x * 1.4426950408889634f, -126.f);
    float r = floorf(y);
    float f = y - r;
    const float c1 = 0.69314718056f, c2 = 0.24022650696f, c3 = 0.05550410866f,
                c4 = 0.00961812911f, c5 = 0.00133335581f, c6 = 0.00015403530f;
    float p = 1.f + f * (c1 + f * (c2 + f * (c3 + f * (c4 + f * (c5 + f * c6)))));
    return p * __int_as_float(((int)r + 127) << 23);
}

// ---------------- weight pre-round -------------------------------------------
__global__ __launch_bounds__(256) void round_tf32_kernel(
    const float* __restrict__ src, float* __restrict__ dst, int n4)
{
    int i = blockIdx.x * blockDim.x + threadIdx.x;
    if (i >= n4) return;
    float4 v = ((const float4*)src)[i];
    v.x = tf32r(v.x); v.y = tf32r(v.y); v.z = tf32r(v.z); v.w = tf32r(v.w);
    ((float4*)dst)[i] = v;
}

// ---------------- LayerNorm (emits tf32-rounded) ------------------------------
__global__ __launch_bounds__(256) void ln_kernel(
    const float* __restrict__ x, const float* __restrict__ w,
    const float* __restrict__ b, float* __restrict__ y)
{
    int row = blockIdx.x;
    const float* xr = x + (size_t)row * DMODEL;
    float v[5];
    float s = 0.f, s2 = 0.f;
#pragma unroll
    for (int j = 0; j < 5; ++j) {
        v[j] = xr[threadIdx.x + j * 256];
        s += v[j];
        s2 += v[j] * v[j];
    }
#pragma unroll
    for (int o = 16; o; o >>= 1) {
        s  += __shfl_xor_sync(0xffffffffu, s,  o);
        s2 += __shfl_xor_sync(0xffffffffu, s2, o);
    }
    __shared__ float sh[16];
    int wid = threadIdx.x >> 5, lane = threadIdx.x & 31;
    if (!lane) { sh[wid] = s; sh[wid + 8] = s2; }
    __syncthreads();
    if (threadIdx.x == 0) {
        float S = 0.f, S2 = 0.f;
#pragma unroll
        for (int i = 0; i < 8; ++i) { S += sh[i]; S2 += sh[i + 8]; }
        sh[0] = S; sh[8] = S2;
    }
    __syncthreads();
    float mean = sh[0] * (1.f / DMODEL);
    float var  = sh[8] * (1.f / DMODEL) - mean * mean;
    float inv  = rsqrtf(var + 1e-6f);
    float* yr = y + (size_t)row * DMODEL;
#pragma unroll
    for (int j = 0; j < 5; ++j) {
        int c = threadIdx.x + j * 256;
        yr[c] = tf32r((v[j] - mean) * inv * w[c] + b[c]);
    }
}

// ---------------- tf32 mma helper ---------------------------------------------
__device__ __forceinline__ void mma_tf32(float* c, const uint32_t* a, const uint32_t* b) {
    asm volatile(
        "mma.sync.aligned.m16n8k8.row.col.f32.tf32.tf32.f32 "
        "{%0,%1,%2,%3}, {%4,%5,%6,%7}, {%8,%9}, {%0,%1,%2,%3};"
        : "+f"(c[0]), "+f"(c[1]), "+f"(c[2]), "+f"(c[3])
        : "r"(a[0]), "r"(a[1]), "r"(a[2]), "r"(a[3]), "r"(b[0]), "r"(b[1]));
}

// -------- Tensorized flash attention with INLINE RoPE (q,k rotated on load) ---
#define KP 84
#define VP 88
#define PP 68
#define ATTN_SMEM ((64 * KP + 64 * VP + 4 * 16 * PP) * 4)

__global__ __launch_bounds__(128) void attn_mma_kernel(
    const float* __restrict__ QKV, const float* __restrict__ cosp,
    const float* __restrict__ sinp, float* __restrict__ O)
{
    extern __shared__ float sm[];
    float* Ks = sm;
    float* Vs = sm + 64 * KP;
    int tid = threadIdx.x;
    int wid = tid >> 5, lane = tid & 31;
    int g = lane >> 2, t = lane & 3;
    float* Ps = sm + 64 * KP + 64 * VP + wid * 16 * PP;

    int qt = blockIdx.x, head = blockIdx.y, seg = blockIdx.z;
    int q0 = seg * LSEG + qt * 64;
    const float scale = 0.11180339887498948f;

    // stage Q tile: rope + scale, coalesced (d and d+-40 are both 16B-aligned)
    for (int i = tid; i < 64 * 20; i += 128) {
        int row = i / 20, d = (i % 20) * 4;
        int tok = q0 + row;
        const float* qb = QKV + (size_t)tok * (3 * DMODEL) + head * HDIM;
        float4 v  = *(const float4*)(qb + d);
        float4 cc = *(const float4*)(cosp + (size_t)tok * HDIM + d);
        float4 ss = *(const float4*)(sinp + (size_t)tok * HDIM + d);
        float4 p;
        float sgn;
        if (d < 40) { p = *(const float4*)(qb + d + 40); sgn = -1.f; }
        else        { p = *(const float4*)(qb + d - 40); sgn =  1.f; }
        float* dst = Ks + row * KP + d;
        dst[0] = (v.x * cc.x + sgn * p.x * ss.x) * scale;
        dst[1] = (v.y * cc.y + sgn * p.y * ss.y) * scale;
        dst[2] = (v.z * cc.z + sgn * p.z * ss.z) * scale;
        dst[3] = (v.w * cc.w + sgn * p.w * ss.w) * scale;
    }
    __syncthreads();

    uint32_t qa[10][4];
    {
        int r0 = wid * 16 + g;
#pragma unroll
        for (int ks = 0; ks < 10; ++ks) {
            qa[ks][0] = __float_as_uint(Ks[r0 * KP + ks * 8 + t]);
            qa[ks][1] = __float_as_uint(Ks[(r0 + 8) * KP + ks * 8 + t]);
            qa[ks][2] = __float_as_uint(Ks[r0 * KP + ks * 8 + t + 4]);
            qa[ks][3] = __float_as_uint(Ks[(r0 + 8) * KP + ks * 8 + t + 4]);
        }
    }
    __syncthreads();

    float oacc[10][4];
#pragma unroll
    for (int nt = 0; nt < 10; ++nt)
#pragma unroll
        for (int q = 0; q < 4; ++q) oacc[nt][q] = 0.f;
    float m0 = -1e30f, m1 = -1e30f, l0 = 0.f, l1 = 0.f;

    for (int kt = 0; kt < LSEG / 64; ++kt) {
        int k0 = seg * LSEG + kt * 64;
        // load K (with inline rope) and V tiles
        for (int i = tid; i < 64 * 20; i += 128) {
            int row = i / 20, d = (i % 20) * 4;
            int tok = k0 + row;
            const float* kb = QKV + (size_t)tok * (3 * DMODEL) + DMODEL + head * HDIM;
            float4 v  = *(const float4*)(kb + d);
            float4 cc = *(const float4*)(cosp + (size_t)tok * HDIM + d);
            float4 ss = *(const float4*)(sinp + (size_t)tok * HDIM + d);
            float4 p;
            float sgn;
            if (d < 40) { p = *(const float4*)(kb + d + 40); sgn = -1.f; }
            else        { p = *(const float4*)(kb + d - 40); sgn =  1.f; }
            float* kp = Ks + row * KP + d;
            kp[0] = v.x * cc.x + sgn * p.x * ss.x;
            kp[1] = v.y * cc.y + sgn * p.y * ss.y;
            kp[2] = v.z * cc.z + sgn * p.z * ss.z;
            kp[3] = v.w * cc.w + sgn * p.w * ss.w;
            float4 vv = *(const float4*)(kb + DMODEL + d);
            *(float4*)(Vs + row * VP + d) = vv;
        }
        __syncthreads();

        float sacc[8][4];
#pragma unroll
        for (int nt = 0; nt < 8; ++nt)
#pragma unroll
            for (int q = 0; q < 4; ++q) sacc[nt][q] = 0.f;
#pragma unroll
        for (int ks = 0; ks < 10; ++ks) {
#pragma unroll
            for (int nt = 0; nt < 8; ++nt) {
                uint32_t bf[2];
                bf[0] = __float_as_uint(Ks[(nt * 8 + g) * KP + ks * 8 + t]);
                bf[1] = __float_as_uint(Ks[(nt * 8 + g) * KP + ks * 8 + t + 4]);
                mma_tf32(sacc[nt], qa[ks], bf);
            }
        }

        float mx0 = sacc[0][0], mx1 = sacc[0][2];
#pragma unroll
        for (int nt = 0; nt < 8; ++nt) {
            mx0 = fmaxf(mx0, fmaxf(sacc[nt][0], sacc[nt][1]));
            mx1 = fmaxf(mx1, fmaxf(sacc[nt][2], sacc[nt][3]));
        }
        mx0 = fmaxf(mx0, __shfl_xor_sync(0xffffffffu, mx0, 1));
        mx0 = fmaxf(mx0, __shfl_xor_sync(0xffffffffu, mx0, 2));
        mx1 = fmaxf(mx1, __shfl_xor_sync(0xffffffffu, mx1, 1));
        mx1 = fmaxf(mx1, __shfl_xor_sync(0xffffffffu, mx1, 2));
        float nm0 = fmaxf(m0, mx0), nm1 = fmaxf(m1, mx1);
        float corr0 = fexp(m0 - nm0), corr1 = fexp(m1 - nm1);
        float ps0 = 0.f, ps1 = 0.f;
#pragma unroll
        for (int nt = 0; nt < 8; ++nt) {
            float p0 = fexp(sacc[nt][0] - nm0);
            float p1 = fexp(sacc[nt][1] - nm0);
            float p2 = fexp(sacc[nt][2] - nm1);
            float p3 = fexp(sacc[nt][3] - nm1);
            ps0 += p0 + p1;
            ps1 += p2 + p3;
            *(float2*)(Ps + g * PP + nt * 8 + 2 * t) = make_float2(p0, p1);
            *(float2*)(Ps + (g + 8) * PP + nt * 8 + 2 * t) = make_float2(p2, p3);
        }
        ps0 += __shfl_xor_sync(0xffffffffu, ps0, 1);
        ps0 += __shfl_xor_sync(0xffffffffu, ps0, 2);
        ps1 += __shfl_xor_sync(0xffffffffu, ps1, 1);
        ps1 += __shfl_xor_sync(0xffffffffu, ps1, 2);
        l0 = l0 * corr0 + ps0;
        l1 = l1 * corr1 + ps1;
        m0 = nm0; m1 = nm1;
#pragma unroll
        for (int nt = 0; nt < 10; ++nt) {
            oacc[nt][0] *= corr0; oacc[nt][1] *= corr0;
            oacc[nt][2] *= corr1; oacc[nt][3] *= corr1;
        }
        __syncwarp();

#pragma unroll
        for (int ks = 0; ks < 8; ++ks) {
            uint32_t af[4];
            af[0] = __float_as_uint(Ps[g * PP + ks * 8 + t]);
            af[1] = __float_as_uint(Ps[(g + 8) * PP + ks * 8 + t]);
            af[2] = __float_as_uint(Ps[g * PP + ks * 8 + t + 4]);
            af[3] = __float_as_uint(Ps[(g + 8) * PP + ks * 8 + t + 4]);
#pragma unroll
            for (int nt = 0; nt < 10; ++nt) {
                uint32_t bf[2];
                bf[0] = __float_as_uint(Vs[(ks * 8 + t) * VP + nt * 8 + g]);
                bf[1] = __float_as_uint(Vs[(ks * 8 + t + 4) * VP + nt * 8 + g]);
                mma_tf32(oacc[nt], af, bf);
            }
        }
        __syncthreads();
    }

    float inv0 = 1.f / l0, inv1 = 1.f / l1;
    int orow = q0 + wid * 16 + g;
#pragma unroll
    for (int nt = 0; nt < 10; ++nt) {
        int col = head * HDIM + nt * 8 + 2 * t;
        *(float2*)(O + (size_t)orow * DMODEL + col) =
            make_float2(tf32r(oacc[nt][0] * inv0), tf32r(oacc[nt][1] * inv0));
        *(float2*)(O + (size_t)(orow + 8) * DMODEL + col) =
            make_float2(tf32r(oacc[nt][2] * inv1), tf32r(oacc[nt][3] * inv1));
    }
}

// ---------------- TF32 pipelined GEMM (Round-10 proven, 4918us config) --------
__device__ __forceinline__ void cp_async16(uint32_t saddr, const void* gptr) {
    asm volatile("cp.async.cg.shared.global [%0], [%1], 16;" :: "r"(saddr), "l"(gptr));
}

#define PITCH 36
#define STAGE_WORDS (2 * 128 * PITCH)
#define GEMM_SMEM (2 * STAGE_WORDS * 4)

__global__ __launch_bounds__(256) void gemm_tf32_pipe(
    const float* __restrict__ A, const float* __restrict__ B,
    const float* __restrict__ bias, const float* __restrict__ res,
    float* __restrict__ C, int M, int N, int K, int epi)
{
    extern __shared__ uint32_t smem[];
    uint32_t smem_base = (uint32_t)__cvta_generic_to_shared(smem);

    int tid = threadIdx.x;
    int wid = tid >> 5, lane = tid & 31;
    int g = lane >> 2, t = lane & 3;
    int mrow0 = (wid >> 2) * 64;
    int ncol0 = (wid & 3) * 32;

    const float* Ag = A + (size_t)(blockIdx.y * 128) * K;
    const float* Bg = B + (size_t)(blockIdx.x * 128) * K;

    int ldrow = tid >> 3;
    int ldkq  = (tid & 7) << 2;

    float acc[4][4][4];
#pragma unroll
    for (int mt = 0; mt < 4; ++mt)
#pragma unroll
        for (int nt = 0; nt < 4; ++nt)
#pragma unroll
            for (int q = 0; q < 4; ++q) acc[mt][nt][q] = 0.f;

    const int NC = K >> 5;

    auto issue = [&](int c, int s) {
        int k0 = c << 5;
        uint32_t sa = smem_base + (uint32_t)s * (STAGE_WORDS * 4);
        uint32_t sb = sa + 128 * PITCH * 4;
#pragma unroll
        for (int i = 0; i < 4; ++i) {
            int row = ldrow + i * 32;
            uint32_t off = ((uint32_t)row * PITCH + ldkq) * 4;
            cp_async16(sa + off, Ag + (size_t)row * K + k0 + ldkq);
            cp_async16(sb + off, Bg + (size_t)row * K + k0 + ldkq);
        }
        asm volatile("cp.async.commit_group;");
    };

    issue(0, 0);

    for (int c = 0; c < NC; ++c) {
        if (c + 1 < NC) {
            issue(c + 1, (c + 1) & 1);
            asm volatile("cp.async.wait_group 1;");
        } else {
            asm volatile("cp.async.wait_group 0;");
        }
        __syncthreads();

        const uint32_t* Asp = smem + (size_t)(c & 1) * STAGE_WORDS;
        const uint32_t* Bsp = Asp + 128 * PITCH;
#pragma unroll
        for (int ks = 0; ks < 4; ++ks) {
            int kb = ks * 8 + t;
            uint32_t af[4][4], bf[4][2];
#pragma unroll
            for (int mt = 0; mt < 4; ++mt) {
                int r = mrow0 + mt * 16 + g;
                af[mt][0] = Asp[r * PITCH + kb];
                af[mt][1] = Asp[(r + 8) * PITCH + kb];
                af[mt][2] = Asp[r * PITCH + kb + 4];
                af[mt][3] = Asp[(r + 8) * PITCH + kb + 4];
            }
#pragma unroll
            for (int nt = 0; nt < 4; ++nt) {
                int cc = ncol0 + nt * 8 + g;
                bf[nt][0] = Bsp[cc * PITCH + kb];
                bf[nt][1] = Bsp[cc * PITCH + kb + 4];
            }
#pragma unroll
            for (int mt = 0; mt < 4; ++mt)
#pragma unroll
                for (int nt = 0; nt < 4; ++nt)
                    mma_tf32(acc[mt][nt], af[mt], bf[nt]);
        }
        __syncthreads();
    }

#pragma unroll
    for (int mt = 0; mt < 4; ++mt) {
#pragma unroll
        for (int nt = 0; nt < 4; ++nt) {
            int row = blockIdx.y * 128 + mrow0 + mt * 16 + g;
            int col = blockIdx.x * 128 + ncol0 + nt * 8 + 2 * t;
            float b0 = bias[col], b1 = bias[col + 1];
#pragma unroll
            for (int half = 0; half < 2; ++half) {
                int r = row + half * 8;
                float v0 = acc[mt][nt][half * 2 + 0] + b0;
                float v1 = acc[mt][nt][half * 2 + 1] + b1;
                if (epi == 1) {
                    const float* rp = res + (size_t)r * N + col;
                    v0 += rp[0];
                    v1 += rp[1];
                } else if (epi == 2) {
                    v0 = tf32r(v0 * (1.f / (1.f + __expf(-v0))));
                    v1 = tf32r(v1 * (1.f / (1.f + __expf(-v1))));
                }
                *(float2*)(C + (size_t)r * N + col) = make_float2(v0, v1);
            }
        }
    }
}

// ---------------- launch ------------------------------------------------------
extern "C" void kernel_launch(void* const* d_in, const int* in_sizes, int n_in,
                              void* d_out, int out_size)
{
    const float* hidden = (const float*)d_in[0];
    const float* cosp   = (const float*)d_in[1];
    const float* sinp   = (const float*)d_in[2];
    const float* ln1w   = (const float*)d_in[3];
    const float* ln1b   = (const float*)d_in[4];
    const float* ln2w   = (const float*)d_in[5];
    const float* ln2b   = (const float*)d_in[6];
    const float* qkvw   = (const float*)d_in[7];
    const float* qkvb   = (const float*)d_in[8];
    const float* projw  = (const float*)d_in[9];
    const float* projb  = (const float*)d_in[10];
    const float* fc1w   = (const float*)d_in[11];
    const float* fc1b   = (const float*)d_in[12];
    const float* fc2w   = (const float*)d_in[13];
    const float* fc2b   = (const float*)d_in[14];
    float* out = (float*)d_out;

    void *pX, *pQKV, *pATT, *pH, *pY, *pG, *pWq, *pWp, *pW1, *pW2;
    cudaGetSymbolAddress(&pX, g_X);
    cudaGetSymbolAddress(&pQKV, g_QKV);
    cudaGetSymbolAddress(&pATT, g_ATT);
    cudaGetSymbolAddress(&pH, g_H);
    cudaGetSymbolAddress(&pY, g_Y);
    cudaGetSymbolAddress(&pG, g_G);
    cudaGetSymbolAddress(&pWq, g_Wq);
    cudaGetSymbolAddress(&pWp, g_Wp);
    cudaGetSymbolAddress(&pW1, g_W1);
    cudaGetSymbolAddress(&pW2, g_W2);
    float* X = (float*)pX;
    float* QKV = (float*)pQKV;
    float* ATT = (float*)pATT;
    float* Hb = (float*)pH;
    float* Y = (float*)pY;
    float* G = (float*)pG;
    float* Wq = (float*)pWq;
    float* Wp = (float*)pWp;
    float* W1 = (float*)pW1;
    float* W2 = (float*)pW2;

    static bool attr_set = false;
    if (!attr_set) {
        cudaFuncSetAttribute(gemm_tf32_pipe,
                             cudaFuncAttributeMaxDynamicSharedMemorySize, GEMM_SMEM);
        cudaFuncSetAttribute(attn_mma_kernel,
                             cudaFuncAttributeMaxDynamicSharedMemorySize, ATTN_SMEM);
        attr_set = true;
    }

    // 0. pre-round weights to tf32
    {
        int n4;
        n4 = 3 * DMODEL * DMODEL / 4;
        round_tf32_kernel<<<(n4 + 255) / 256, 256>>>(qkvw, Wq, n4);
        n4 = DMODEL * DMODEL / 4;
        round_tf32_kernel<<<(n4 + 255) / 256, 256>>>(projw, Wp, n4);
        n4 = IDIM * DMODEL / 4;
        round_tf32_kernel<<<(n4 + 255) / 256, 256>>>(fc1w, W1, n4);
        round_tf32_kernel<<<(n4 + 255) / 256, 256>>>(fc2w, W2, n4);
    }

    // 1. ln1
    ln_kernel<<<T_TOK, 256>>>(hidden, ln1w, ln1b, X);
    // 2. qkv = X @ qkv_w^T + qkv_b   (un-roped; rope applied inside attention)
    gemm_tf32_pipe<<<dim3(3 * DMODEL / 128, T_TOK / 128), 256, GEMM_SMEM>>>(
        X, Wq, qkvb, nullptr, QKV, T_TOK, 3 * DMODEL, DMODEL, 0);
    // 3. tensorized attention with inline rope
    attn_mma_kernel<<<dim3(LSEG / 64, NHEAD, NSEG), 128, ATTN_SMEM>>>(
        QKV, cosp, sinp, ATT);
    // 4. h = hidden + ATT @ proj_w^T + proj_b
    gemm_tf32_pipe<<<dim3(DMODEL / 128, T_TOK / 128), 256, GEMM_SMEM>>>(
        ATT, Wp, projb, hidden, Hb, T_TOK, DMODEL, DMODEL, 1);
    // 5. ln2
    ln_kernel<<<T_TOK, 256>>>(Hb, ln2w, ln2b, Y);
    // 6. G = silu(Y @ fc1_w^T + fc1_b)
    gemm_tf32_pipe<<<dim3(IDIM / 128, T_TOK / 128), 256, GEMM_SMEM>>>(
        Y, W1, fc1b, nullptr, G, T_TOK, IDIM, DMODEL, 2);
    // 7. out = h + G @ fc2_w^T + fc2_b
    gemm_tf32_pipe<<<dim3(DMODEL / 128, T_TOK / 128), 256, GEMM_SMEM>>>(
        G, W2, fc2b, Hb, out, T_TOK, DMODEL, IDIM, 1);
}